// round 11
// baseline (speedup 1.0000x reference)
#include <cuda_runtime.h>
#include <cuda_bf16.h>
#include <cstdint>

// Problem dims (fixed by the dataset)
#define BB 32
#define SS 1024
#define II 256
#define HH 512
#define OO 256
#define MROWS (BB * SS)   // 32768

#define CH 32             // rows per bulk-copy chunk (one per warp-0 lane)

// Dynamic smem layout for the scan kernel
#define SMEM_WBUF   0                       // 2 bufs x 32 rows x 2048 B
#define SMEM_LIST   (2 * CH * 2048)         // 131072: 512 ints
#define SMEM_MASKS  (SMEM_LIST + 2048)      // 133120: 16 u32
#define SMEM_MBAR   (SMEM_MASKS + 64)       // 133184: 2 x u64 (8-aligned)
#define SMEM_TOTAL  (SMEM_MBAR + 64)

// Scratch (allocation-free rule: __device__ globals)
__device__ float g_ic[(size_t)MROWS * HH];   // 64 MB input currents
__device__ float g_spk[(size_t)MROWS * HH];  // 64 MB spikes (fp32 0/1)

// ---------------------------------------------------------------------------
// Register-blocked SGEMM: C[M,N] = A[M,K] @ B[K,N], all row-major fp32.
// BM=128, BN=64, BK=16, TM=8, TN=4, 256 threads (proven config).
// ---------------------------------------------------------------------------
template <int BM, int BN, int BK, int TM, int TN>
__global__ __launch_bounds__(256) void sgemm_kernel(
    const float* __restrict__ A, const float* __restrict__ Bm,
    float* __restrict__ C, int M, int N, int K)
{
    __shared__ float As[BK][BM];
    __shared__ float Bs[BK][BN];

    const int tid = threadIdx.x;
    const int mBlock = blockIdx.y * BM;
    const int nBlock = blockIdx.x * BN;

    const int tCols = BN / TN;
    const int tRow = tid / tCols;
    const int tCol = tid % tCols;

    float acc[TM][TN];
#pragma unroll
    for (int i = 0; i < TM; i++)
#pragma unroll
        for (int j = 0; j < TN; j++) acc[i][j] = 0.f;

    for (int k0 = 0; k0 < K; k0 += BK) {
#pragma unroll
        for (int it = 0; it < (BM * BK) / (256 * 4); it++) {
            int f = tid + it * 256;
            int m = f / (BK / 4);
            int kq = f % (BK / 4);
            float4 v = *reinterpret_cast<const float4*>(
                &A[(size_t)(mBlock + m) * K + k0 + kq * 4]);
            As[kq * 4 + 0][m] = v.x;
            As[kq * 4 + 1][m] = v.y;
            As[kq * 4 + 2][m] = v.z;
            As[kq * 4 + 3][m] = v.w;
        }
#pragma unroll
        for (int it = 0; it < (BK * BN) / (256 * 4); it++) {
            int f = tid + it * 256;
            int k = f / (BN / 4);
            int nq = f % (BN / 4);
            float4 v = *reinterpret_cast<const float4*>(
                &Bm[(size_t)(k0 + k) * N + nBlock + nq * 4]);
            *reinterpret_cast<float4*>(&Bs[k][nq * 4]) = v;
        }
        __syncthreads();

#pragma unroll
        for (int k = 0; k < BK; k++) {
            float ra[TM], rb[TN];
#pragma unroll
            for (int i = 0; i < TM; i++) ra[i] = As[k][tRow * TM + i];
#pragma unroll
            for (int j = 0; j < TN; j++) rb[j] = Bs[k][tCol * TN + j];
#pragma unroll
            for (int i = 0; i < TM; i++)
#pragma unroll
                for (int j = 0; j < TN; j++) acc[i][j] += ra[i] * rb[j];
        }
        __syncthreads();
    }

#pragma unroll
    for (int i = 0; i < TM; i++) {
        float* crow = &C[(size_t)(mBlock + tRow * TM + i) * N + nBlock + tCol * TN];
#pragma unroll
        for (int j = 0; j < TN; j += 4) {
            float4 v = make_float4(acc[i][j], acc[i][j + 1], acc[i][j + 2], acc[i][j + 3]);
            *reinterpret_cast<float4*>(&crow[j]) = v;
        }
    }
}

// ---------------------------------------------------------------------------
// PTX helpers
// ---------------------------------------------------------------------------
__device__ __forceinline__ uint32_t smem_addr_u32(const void* p) {
    uint32_t a;
    asm("{ .reg .u64 t; cvta.to.shared.u64 t, %1; cvt.u32.u64 %0, t; }"
        : "=r"(a) : "l"(p));
    return a;
}

__device__ __forceinline__ void mbar_init(uint32_t bar, uint32_t count) {
    asm volatile("mbarrier.init.shared.b64 [%0], %1;" :: "r"(bar), "r"(count) : "memory");
}

__device__ __forceinline__ void mbar_expect_tx(uint32_t bar, uint32_t bytes) {
    asm volatile("mbarrier.arrive.expect_tx.shared.b64 _, [%0], %1;"
                 :: "r"(bar), "r"(bytes) : "memory");
}

__device__ __forceinline__ void mbar_wait_parity(uint32_t bar, uint32_t parity) {
    asm volatile(
        "{\n\t"
        ".reg .pred P;\n\t"
        "WL_%=:\n\t"
        "mbarrier.try_wait.parity.acquire.cta.shared::cta.b64 P, [%0], %1, 0x989680;\n\t"
        "@P bra WD_%=;\n\t"
        "bra WL_%=;\n\t"
        "WD_%=:\n\t"
        "}"
        :: "r"(bar), "r"(parity) : "memory");
}

__device__ __forceinline__ void bulk_copy_row(uint32_t dst_smem, const void* src,
                                              uint32_t bytes, uint32_t bar) {
    asm volatile(
        "cp.async.bulk.shared::cluster.global.mbarrier::complete_tx::bytes "
        "[%0], [%1], %2, [%3];"
        :: "r"(dst_smem), "l"(src), "r"(bytes), "r"(bar) : "memory");
}

// ---------------------------------------------------------------------------
// Recurrent scan. One CTA per batch (32 CTAs), 512 threads (thread = column h).
// lateral[h] = sum_{j in firing} W_lat[j,h].
//  - rows [0,32): direct coalesced LDG.32 (hides bulk-copy latency of chunk 0)
//  - rows [32,ns): double-buffered cp.async.bulk chunks (32 rows = 64KB) into
//    smem, accumulated via conflict-free LDS.32 (crossbar 128B/cyc, i.e. ~2x
//    the LDG.128 L1 replay-path ~65B/cyc that bounded previous rounds).
// Thread-per-column => no partial-sum reduction barrier at all.
// ---------------------------------------------------------------------------
__global__ __launch_bounds__(512, 1) void snn_scan_kernel(
    const float* __restrict__ ic, const float* __restrict__ Wlat,
    const float* __restrict__ thr, float* __restrict__ spk)
{
    extern __shared__ char sm[];
    float* wbuf = reinterpret_cast<float*>(sm + SMEM_WBUF);     // [2][CH][HH]
    int* list_s = reinterpret_cast<int*>(sm + SMEM_LIST);
    unsigned* masks_s = reinterpret_cast<unsigned*>(sm + SMEM_MASKS);
    const uint32_t wbuf_a = smem_addr_u32(sm + SMEM_WBUF);
    const uint32_t mbar_a = smem_addr_u32(sm + SMEM_MBAR);      // 2 barriers

    const int b = blockIdx.x;
    const int tid = threadIdx.x;           // 0..511
    const int lane = tid & 31;
    const int warp = tid >> 5;             // 0..15

    if (tid == 0) {
        mbar_init(mbar_a, 1);
        mbar_init(mbar_a + 8, 1);
    }
    __syncthreads();

    int phase[2] = {0, 0};

    float mp = 0.f;
    int refrac = 0;
    int ns = 0;
    const float thrv = thr[tid];

    const size_t rowbase = (size_t)b * SS * HH;
    float ic_cur = ic[rowbase + tid];
    const float* Wcol = Wlat + tid;        // column tid, stride HH

    for (int t = 0; t < SS; ++t) {
        float ic_nxt = (t < SS - 1) ? ic[rowbase + (size_t)(t + 1) * HH + tid] : 0.f;

        const int nd = (ns < CH) ? ns : CH;      // direct rows
        const int ntma = ns - nd;                // bulk-copied rows
        const int nch = (ntma + CH - 1) / CH;

        // --- issue bulk chunk 0 (rows [CH, 2*CH)) ASAP ---
        if (nch > 0) {
            if (tid < 32) {
                const int base = CH;
                const int cnt = (ntma < CH) ? ntma : CH;
                asm volatile("fence.proxy.async.shared::cta;" ::: "memory");
                if (tid == 0) mbar_expect_tx(mbar_a, (uint32_t)cnt * 2048u);
                __syncwarp();
                if (tid < cnt) {
                    int row = list_s[base + tid];
                    bulk_copy_row(wbuf_a + (uint32_t)tid * 2048u,
                                  Wlat + (size_t)row * HH, 2048u, mbar_a);
                }
            }
        }

        // --- direct accumulate rows [0, nd) while the bulk copy flies ---
        float l0 = 0.f, l1 = 0.f, l2 = 0.f, l3 = 0.f;
        {
            int r = 0;
            for (; r + 3 < nd; r += 4) {
                int j0 = list_s[r], j1 = list_s[r + 1];
                int j2 = list_s[r + 2], j3 = list_s[r + 3];
                l0 += Wcol[(size_t)j0 * HH];
                l1 += Wcol[(size_t)j1 * HH];
                l2 += Wcol[(size_t)j2 * HH];
                l3 += Wcol[(size_t)j3 * HH];
            }
            for (; r < nd; ++r) l0 += Wcol[(size_t)list_s[r] * HH];
        }

        // --- bulk chunks: prefetch next, wait, accumulate from smem ---
        for (int c = 0; c < nch; ++c) {
            const int buf = c & 1;
            if (c + 1 < nch) {
                if (tid < 32) {
                    const int base = CH + (c + 1) * CH;
                    int cnt = ntma - (c + 1) * CH;
                    if (cnt > CH) cnt = CH;
                    const int nbuf = (c + 1) & 1;
                    const uint32_t bar = mbar_a + 8u * (uint32_t)nbuf;
                    asm volatile("fence.proxy.async.shared::cta;" ::: "memory");
                    if (tid == 0) mbar_expect_tx(bar, (uint32_t)cnt * 2048u);
                    __syncwarp();
                    if (tid < cnt) {
                        int row = list_s[base + tid];
                        bulk_copy_row(wbuf_a + (uint32_t)(nbuf * CH + tid) * 2048u,
                                      Wlat + (size_t)row * HH, 2048u, bar);
                    }
                }
            }
            mbar_wait_parity(mbar_a + 8u * (uint32_t)buf, (uint32_t)phase[buf]);
            phase[buf] ^= 1;

            int cnt = ntma - c * CH;
            if (cnt > CH) cnt = CH;
            const float* rows = wbuf + (size_t)buf * CH * HH;
            int r = 0;
            for (; r + 3 < cnt; r += 4) {
                l0 += rows[(r + 0) * HH + tid];
                l1 += rows[(r + 1) * HH + tid];
                l2 += rows[(r + 2) * HH + tid];
                l3 += rows[(r + 3) * HH + tid];
            }
            for (; r < cnt; ++r) l0 += rows[r * HH + tid];
            __syncthreads();   // all reads of buf done before it is refetched
        }
        float lat = (l0 + l1) + (l2 + l3);

        // --- membrane update (reference semantics, fp32) ---
        mp = 0.95f * mp + ic_cur - lat;
        if (refrac > 0) mp = 0.f;
        refrac = (refrac > 0) ? (refrac - 1) : 0;
        bool spike = (mp >= thrv);
        spk[rowbase + (size_t)t * HH + tid] = spike ? 1.f : 0.f;
        if (spike) { mp = 0.f; refrac = 2; }

        // --- rebuild firing list (ballots + prefix over 16 words) ---
        unsigned m = __ballot_sync(0xffffffffu, spike);
        if (lane == 0) masks_s[warp] = m;
        __syncthreads();                       // masks visible

        int tot = 0, base = 0;
#pragma unroll
        for (int w = 0; w < 16; ++w) {
            if (w == warp) base = tot;
            tot += __popc(masks_s[w]);
        }
        if (spike) {
            int pos = base + __popc(m & ((1u << lane) - 1u));
            list_s[pos] = tid;
        }
        ns = tot;
        ic_cur = ic_nxt;
        __syncthreads();                       // list visible for next step
    }
}

// ---------------------------------------------------------------------------
// Launch
// ---------------------------------------------------------------------------
extern "C" void kernel_launch(void* const* d_in, const int* in_sizes, int n_in,
                              void* d_out, int out_size)
{
    const float* x    = (const float*)d_in[0];  // [B,S,I]
    const float* Win  = (const float*)d_in[1];  // [I,H]
    const float* Wlat = (const float*)d_in[2];  // [H,H]
    const float* Wout = (const float*)d_in[3];  // [H,O]
    const float* thr  = (const float*)d_in[4];  // [H]
    float* out = (float*)d_out;                 // [B,S,O]

    float *ic, *spk;
    cudaGetSymbolAddress((void**)&ic, g_ic);
    cudaGetSymbolAddress((void**)&spk, g_spk);

    cudaFuncSetAttribute(snn_scan_kernel,
                         cudaFuncAttributeMaxDynamicSharedMemorySize, SMEM_TOTAL);

    // GEMM1: ic = x @ Win   (32768 x 512 x 256)
    {
        dim3 grid(HH / 64, MROWS / 128);
        sgemm_kernel<128, 64, 16, 8, 4><<<grid, 256>>>(x, Win, ic, MROWS, HH, II);
    }

    // Scan: 32 CTAs x 512 threads, 133KB dynamic smem
    snn_scan_kernel<<<BB, 512, SMEM_TOTAL>>>(ic, Wlat, thr, spk);

    // GEMM3: out = spk @ Wout   (32768 x 256 x 512)
    {
        dim3 grid(OO / 64, MROWS / 128);
        sgemm_kernel<128, 64, 16, 8, 4><<<grid, 256>>>(spk, Wout, out, MROWS, OO, HH);
    }
}